// round 10
// baseline (speedup 1.0000x reference)
#include <cuda_runtime.h>
#include <math.h>

// Problem constants
#define Nn 128
#define Cc 64
#define Tt 128
#define Vv 25
#define Rr 8
#define Hh 12

// Scratch (device globals; no allocation allowed)
__device__ float g_xm[Nn * Cc * Vv];             // mean over T        (0.8 MB)
__device__ float g_rel[Nn * Rr * Vv * Vv];       // tanh relation      (2.56 MB, L2-resident)
__device__ float g_a[Nn * Vv];                   // SE joint gate      (12.8 KB)

// ================= Kernel 1: xm[n,c,v] = mean_t x[n,c,t,v] =================
// Proven: 19.7us @ ~70% DRAM. Thread j loads float4s at j, j+200, j+400,
// j+600 (stride 800 floats == 0 mod 25 -> fixed v per component), then a
// conflict-free stride-25 shared reduction.
__global__ void __launch_bounds__(200) k1_meanT(const float* __restrict__ x) {
    const int b = blockIdx.x;                 // n*C + c
    const int j = threadIdx.x;                // 0..199
    const float4* xp4 = reinterpret_cast<const float4*>(x + (size_t)b * (Tt * Vv));

    float4 a0 = xp4[j];
    float4 a1 = xp4[j + 200];
    float4 a2 = xp4[j + 400];
    float4 a3 = xp4[j + 600];

    __shared__ float red[800];
    red[4 * j + 0] = a0.x + a1.x + a2.x + a3.x;
    red[4 * j + 1] = a0.y + a1.y + a2.y + a3.y;
    red[4 * j + 2] = a0.z + a1.z + a2.z + a3.z;
    red[4 * j + 3] = a0.w + a1.w + a2.w + a3.w;
    __syncthreads();

    if (j < Vv) {
        float tot = 0.f;
        #pragma unroll
        for (int p = 0; p < 32; p++) tot += red[j + Vv * p];
        g_xm[b * Vv + j] = tot * (1.0f / Tt);
    }
}

// ============ Kernel 2 (small): SE gate + relation tensor ============
// One block per n, 256 threads. Writes g_a[n,v] and g_rel[n,r,u,v].
__global__ void k2_rel(const float* __restrict__ w1, const float* __restrict__ b1,
                       const float* __restrict__ w2, const float* __restrict__ b2,
                       const float* __restrict__ sw1, const float* __restrict__ sb1,
                       const float* __restrict__ sw2, const float* __restrict__ sb2) {
    const int n = blockIdx.x;
    const int tid = threadIdx.x;
    const int NT = 256;

    __shared__ float xm_sh[Cc * Vv];
    __shared__ float w1s[Rr * Cc], w2s[Rr * Cc];
    __shared__ float sw1s[Hh * Vv], sw2s[Vv * Hh];
    __shared__ float b1s[Rr], b2s[Rr], sb1s[Hh], sb2s[Vv];
    __shared__ float s_sh[Vv], h_sh[Hh];
    __shared__ float x1_sh[Rr * Vv], x2_sh[Rr * Vv];

    for (int i = tid; i < Cc * Vv; i += NT) xm_sh[i] = g_xm[n * Cc * Vv + i];
    for (int i = tid; i < Rr * Cc; i += NT) { w1s[i] = w1[i]; w2s[i] = w2[i]; }
    for (int i = tid; i < Hh * Vv; i += NT) { sw1s[i] = sw1[i]; sw2s[i] = sw2[i]; }
    if (tid < Rr) { b1s[tid] = b1[tid]; b2s[tid] = b2[tid]; }
    if (tid < Hh) sb1s[tid] = sb1[tid];
    if (tid < Vv) sb2s[tid] = sb2[tid];
    __syncthreads();

    if (tid < Vv) {
        float acc = 0.f;
        for (int c = 0; c < Cc; c++) acc += xm_sh[c * Vv + tid];
        s_sh[tid] = acc * (1.0f / Cc);
    }
    __syncthreads();
    if (tid < Hh) {
        float acc = sb1s[tid];
        for (int v = 0; v < Vv; v++) acc += sw1s[tid * Vv + v] * s_sh[v];
        h_sh[tid] = fmaxf(acc, 0.f);
    }
    __syncthreads();
    if (tid < Vv) {
        float acc = sb2s[tid];
        for (int q = 0; q < Hh; q++) acc += sw2s[tid * Hh + q] * h_sh[q];
        g_a[n * Vv + tid] = 1.0f / (1.0f + expf(-acc));
    }

    if (tid < Rr * Vv) {
        int r = tid / Vv, v = tid % Vv;
        float acc1 = b1s[r], acc2 = b2s[r];
        for (int c = 0; c < Cc; c++) {
            float xm = xm_sh[c * Vv + v];
            acc1 += w1s[r * Cc + c] * xm;
            acc2 += w2s[r * Cc + c] * xm;
        }
        x1_sh[tid] = acc1;
        x2_sh[tid] = acc2;
    }
    __syncthreads();

    float* relp = g_rel + (size_t)n * (Rr * Vv * Vv);
    for (int i = tid; i < Rr * Vv * Vv; i += NT) {
        int r = i / (Vv * Vv), rem = i % (Vv * Vv);
        int u = rem / Vv, v = rem % Vv;
        relp[i] = tanhf(x1_sh[r * Vv + u] - x2_sh[r * Vv + v]);
    }
}

// ============ Kernel 3 v6: 2D register-tiled GEMM ============
// One block per (n,c), 128 threads. Thread (tg, ug) computes a 4t x 8u output
// tile: its 4 t-rows (floats 100q..100q+99, float4-aligned) are cached in 100
// registers; weights come from WT[v][u] (transposed, row stride 36 floats so
// each ug's 8 weights = 2 aligned LDS.128, ~1 wavefront each). Inner loop per
// v: 2 LDS.128 + 32 FMA. Per-thread weight-LDS drops 175 -> 50 vs v2.
#define WTS 36   // WT row stride in floats (float4-aligned, bank-spread)
__global__ void __launch_bounds__(128) k3_gemm(const float* __restrict__ x,
                                               const float* __restrict__ Astat,
                                               const float* __restrict__ w4,
                                               const float* __restrict__ b4,
                                               float* __restrict__ out) {
    __shared__ float xs[Tt * Vv];                      // 12.8 KB; reused as out staging
    __shared__ __align__(16) float WT[Vv * WTS];       // 3.6 KB transposed weights

    const int b = blockIdx.x;           // n*C + c
    const int n = b >> 6;
    const int c = b & 63;
    const int tid = threadIdx.x;
    const int lane = tid & 31;
    const int w = tid >> 5;
    const int tg = lane & 7;            // 0..7
    const int ug = lane >> 3;           // 0..3  -> u in [8*ug, 8*ug+8)
    const int q = w * 8 + tg;           // 0..31 -> rows 4q..4q+3

    // ---- Stage 1: load x tile (coalesced float4) ----
    const float4* xp4 = reinterpret_cast<const float4*>(x + (size_t)b * (Tt * Vv));
    float4* xs4 = reinterpret_cast<float4*>(xs);
    #pragma unroll
    for (int i = tid; i < (Tt * Vv) / 4; i += 128) xs4[i] = xp4[i];

    // ---- Stage 2: reconstruct transposed weights into WT ----
    // WT[v*36 + u] = (b4[c] + A[u,v] + sum_r w4[c,r]*rel[n,r,u,v]) * a[n,v]
    {
        float w4c[Rr];
        #pragma unroll
        for (int r = 0; r < Rr; r++) w4c[r] = __ldg(w4 + c * Rr + r);
        const float bias = __ldg(b4 + c);
        const float* relp = g_rel + (size_t)n * (Rr * Vv * Vv);
        const float* ap = g_a + n * Vv;
        // zero the padding u = 25..31 (read by ug=3 lanes)
        for (int i = tid; i < Vv * 7; i += 128) {
            int v = i / 7, u = 25 + i % 7;
            WT[v * WTS + u] = 0.f;
        }
        #pragma unroll 1
        for (int e = tid; e < Vv * Vv; e += 128) {    // e = u*25 + v (v fastest: coalesced rel)
            int u = e / Vv, v = e % Vv;
            float acc = bias + __ldg(Astat + e);
            #pragma unroll
            for (int r = 0; r < Rr; r++) acc += w4c[r] * relp[r * (Vv * Vv) + e];
            WT[v * WTS + u] = acc * __ldg(ap + v);
        }
    }
    __syncthreads();

    // ---- Stage 3: pull this thread's 4 t-rows into registers ----
    // rows 4q..4q+3 = floats [100q, 100q+100) = float4 [25q, 25q+25): aligned,
    // 8 distinct addresses per instr (bank groups 4q) + 4-way ug broadcast.
    float xr[100];
    #pragma unroll
    for (int i = 0; i < 25; i++) {
        float4 t4 = xs4[q * 25 + i];
        xr[4 * i + 0] = t4.x;
        xr[4 * i + 1] = t4.y;
        xr[4 * i + 2] = t4.z;
        xr[4 * i + 3] = t4.w;
    }
    __syncthreads();   // xs now free for output staging

    // ---- Stage 4: 4x8 register-tile GEMM ----
    const float4* wt4 = reinterpret_cast<const float4*>(WT);   // row = 9 float4
    float acc[4][8];
    #pragma unroll
    for (int r = 0; r < 4; r++)
        #pragma unroll
        for (int j = 0; j < 8; j++) acc[r][j] = 0.f;

    #pragma unroll
    for (int v = 0; v < Vv; v++) {
        const float4 wa = wt4[v * (WTS / 4) + 2 * ug];
        const float4 wb = wt4[v * (WTS / 4) + 2 * ug + 1];
        #pragma unroll
        for (int r = 0; r < 4; r++) {
            // xr[r*25+v]: note xr[k] holds row k/25, col k%25 of the 4-row slab
            const float xx = xr[r * 25 + v];
            acc[r][0] += wa.x * xx;
            acc[r][1] += wa.y * xx;
            acc[r][2] += wa.z * xx;
            acc[r][3] += wa.w * xx;
            acc[r][4] += wb.x * xx;
            acc[r][5] += wb.y * xx;
            acc[r][6] += wb.z * xx;
            acc[r][7] += wb.w * xx;
        }
    }

    // ---- Stage 5: stage outputs in xs, then coalesced store ----
    #pragma unroll
    for (int r = 0; r < 4; r++) {
        #pragma unroll
        for (int j = 0; j < 8; j++) {
            const int u = ug * 8 + j;
            if (u < Vv) xs[(4 * q + r) * Vv + u] = acc[r][j];
        }
    }
    __syncthreads();

    float4* op4 = reinterpret_cast<float4*>(out + (size_t)b * (Tt * Vv));
    #pragma unroll
    for (int i = tid; i < (Tt * Vv) / 4; i += 128) __stcs(op4 + i, xs4[i]);
}

extern "C" void kernel_launch(void* const* d_in, const int* in_sizes, int n_in,
                              void* d_out, int out_size) {
    const float* x   = (const float*)d_in[0];
    const float* A   = (const float*)d_in[1];
    const float* w1  = (const float*)d_in[2];
    const float* b1  = (const float*)d_in[3];
    const float* w2  = (const float*)d_in[4];
    const float* b2  = (const float*)d_in[5];
    const float* w4  = (const float*)d_in[6];
    const float* b4  = (const float*)d_in[7];
    const float* sw1 = (const float*)d_in[8];
    const float* sb1 = (const float*)d_in[9];
    const float* sw2 = (const float*)d_in[10];
    const float* sb2 = (const float*)d_in[11];
    float* out = (float*)d_out;

    k1_meanT<<<Nn * Cc, 200>>>(x);
    k2_rel<<<Nn, 256>>>(w1, b1, w2, b2, sw1, sb1, sw2, sb2);
    k3_gemm<<<Nn * Cc, 128>>>(x, A, w4, b4, out);
}

// round 11
// speedup vs baseline: 1.2898x; 1.2898x over previous
#include <cuda_runtime.h>
#include <math.h>

// Problem constants
#define Nn 128
#define Cc 64
#define Tt 128
#define Vv 25
#define Rr 8
#define Hh 12

// Scratch (device globals; no allocation allowed)
__device__ float g_xm[Nn * Cc * Vv];             // mean over T        (0.8 MB)
__device__ float g_rel[Nn * Rr * Vv * Vv];       // tanh relation      (2.56 MB, L2-resident)
__device__ float g_a[Nn * Vv];                   // SE joint gate      (12.8 KB)

// ================= Kernel 1: xm[n,c,v] = mean_t x[n,c,t,v] =================
// Proven: ~19.5us @ ~71% DRAM (practical streaming ceiling). Thread j loads
// float4s at j, j+200, j+400, j+600 (stride 800 floats == 0 mod 25 -> fixed v
// per component), then a conflict-free stride-25 shared reduction.
__global__ void __launch_bounds__(200) k1_meanT(const float* __restrict__ x) {
    const int b = blockIdx.x;                 // n*C + c
    const int j = threadIdx.x;                // 0..199
    const float4* xp4 = reinterpret_cast<const float4*>(x + (size_t)b * (Tt * Vv));

    float4 a0 = xp4[j];
    float4 a1 = xp4[j + 200];
    float4 a2 = xp4[j + 400];
    float4 a3 = xp4[j + 600];

    __shared__ float red[800];
    red[4 * j + 0] = a0.x + a1.x + a2.x + a3.x;
    red[4 * j + 1] = a0.y + a1.y + a2.y + a3.y;
    red[4 * j + 2] = a0.z + a1.z + a2.z + a3.z;
    red[4 * j + 3] = a0.w + a1.w + a2.w + a3.w;
    __syncthreads();

    if (j < Vv) {
        float tot = 0.f;
        #pragma unroll
        for (int p = 0; p < 32; p++) tot += red[j + Vv * p];
        g_xm[b * Vv + j] = tot * (1.0f / Tt);
    }
}

// ============ Kernel 2 (small): SE gate + relation tensor ============
// One block per n, 256 threads. Writes g_a[n,v] and g_rel[n,r,u,v].
// No Aeff materialization — k3 reconstructs its weight matrix from rel.
__global__ void k2_rel(const float* __restrict__ w1, const float* __restrict__ b1,
                       const float* __restrict__ w2, const float* __restrict__ b2,
                       const float* __restrict__ sw1, const float* __restrict__ sb1,
                       const float* __restrict__ sw2, const float* __restrict__ sb2) {
    const int n = blockIdx.x;
    const int tid = threadIdx.x;
    const int NT = 256;

    __shared__ float xm_sh[Cc * Vv];
    __shared__ float w1s[Rr * Cc], w2s[Rr * Cc];
    __shared__ float sw1s[Hh * Vv], sw2s[Vv * Hh];
    __shared__ float b1s[Rr], b2s[Rr], sb1s[Hh], sb2s[Vv];
    __shared__ float s_sh[Vv], h_sh[Hh];
    __shared__ float x1_sh[Rr * Vv], x2_sh[Rr * Vv];

    for (int i = tid; i < Cc * Vv; i += NT) xm_sh[i] = g_xm[n * Cc * Vv + i];
    for (int i = tid; i < Rr * Cc; i += NT) { w1s[i] = w1[i]; w2s[i] = w2[i]; }
    for (int i = tid; i < Hh * Vv; i += NT) { sw1s[i] = sw1[i]; sw2s[i] = sw2[i]; }
    if (tid < Rr) { b1s[tid] = b1[tid]; b2s[tid] = b2[tid]; }
    if (tid < Hh) sb1s[tid] = sb1[tid];
    if (tid < Vv) sb2s[tid] = sb2[tid];
    __syncthreads();

    if (tid < Vv) {
        float acc = 0.f;
        for (int c = 0; c < Cc; c++) acc += xm_sh[c * Vv + tid];
        s_sh[tid] = acc * (1.0f / Cc);
    }
    __syncthreads();
    if (tid < Hh) {
        float acc = sb1s[tid];
        for (int v = 0; v < Vv; v++) acc += sw1s[tid * Vv + v] * s_sh[v];
        h_sh[tid] = fmaxf(acc, 0.f);
    }
    __syncthreads();
    if (tid < Vv) {
        float acc = sb2s[tid];
        for (int q = 0; q < Hh; q++) acc += sw2s[tid * Hh + q] * h_sh[q];
        g_a[n * Vv + tid] = 1.0f / (1.0f + expf(-acc));
    }

    if (tid < Rr * Vv) {
        int r = tid / Vv, v = tid % Vv;
        float acc1 = b1s[r], acc2 = b2s[r];
        for (int c = 0; c < Cc; c++) {
            float xm = xm_sh[c * Vv + v];
            acc1 += w1s[r * Cc + c] * xm;
            acc2 += w2s[r * Cc + c] * xm;
        }
        x1_sh[tid] = acc1;
        x2_sh[tid] = acc2;
    }
    __syncthreads();

    float* relp = g_rel + (size_t)n * (Rr * Vv * Vv);
    for (int i = tid; i < Rr * Vv * Vv; i += NT) {
        int r = i / (Vv * Vv), rem = i % (Vv * Vv);
        int u = rem / Vv, v = rem % Vv;
        relp[i] = tanhf(x1_sh[r * Vv + u] - x2_sh[r * Vv + v]);
    }
}

// ============ Kernel 3 (v5 + lb(128,10), measured 70.3us): recon + GEMM ============
// One block per (n,c), 128 threads, one t-row per thread. launch_bounds
// (128,10) caps regs at 51 (compiles to 48, no spills) so >=10 blocks/SM.
__global__ void __launch_bounds__(128, 10) k3_gemm(const float* __restrict__ x,
                                                   const float* __restrict__ Astat,
                                                   const float* __restrict__ w4,
                                                   const float* __restrict__ b4,
                                                   float* __restrict__ out) {
    __shared__ float xs[Tt * Vv];                      // 12.8 KB; reused as out staging
    __shared__ __align__(16) float Ws[Vv * 28];        // padded rows: 112 B each

    const int b = blockIdx.x;           // n*C + c
    const int n = b >> 6;
    const int c = b & 63;
    const int tid = threadIdx.x;        // 0..127 == t

    // Load x tile (800 float4, coalesced; the only cold-DRAM read)
    const float4* xp4 = reinterpret_cast<const float4*>(x + (size_t)b * (Tt * Vv));
    float4* xs4 = reinterpret_cast<float4*>(xs);
    #pragma unroll
    for (int i = tid; i < (Tt * Vv) / 4; i += 128) xs4[i] = xp4[i];

    // Zero padding columns 25..27 of Ws
    if (tid < Vv * 3) {
        int u = tid / 3, p = tid % 3;
        Ws[u * 28 + 25 + p] = 0.f;
    }

    // Reconstruct weight matrix from rel (all operands L2-resident):
    // Ws[u,v] = (sum_r w4[c,r]*rel[n,r,u,v] + b4[c] + A[u,v]) * a[n,v]
    {
        float w4c[Rr];
        #pragma unroll
        for (int r = 0; r < Rr; r++) w4c[r] = __ldg(w4 + c * Rr + r);
        const float bias = __ldg(b4 + c);
        const float* relp = g_rel + (size_t)n * (Rr * Vv * Vv);
        const float* ap = g_a + n * Vv;
        #pragma unroll 1
        for (int e = tid; e < Vv * Vv; e += 128) {
            int u = e / Vv, v = e % Vv;
            float acc = bias + __ldg(Astat + e);
            #pragma unroll
            for (int r = 0; r < Rr; r++) acc += w4c[r] * relp[r * (Vv * Vv) + e];
            Ws[u * 28 + v] = acc * __ldg(ap + v);
        }
    }
    __syncthreads();

    // Pull this thread's x row into registers (lane stride 25 ⊥ 32: conflict-free)
    float xv[Vv];
    #pragma unroll
    for (int v = 0; v < Vv; v++) xv[v] = xs[tid * Vv + v];
    __syncthreads();   // xs now free for output staging

    #pragma unroll 1
    for (int u = 0; u < Vv; u++) {
        const float4* wr = reinterpret_cast<const float4*>(Ws + u * 28);
        float4 w0 = wr[0], w1 = wr[1], w2 = wr[2], w3 = wr[3];
        float4 w4r = wr[4], w5 = wr[5], w6 = wr[6];
        float acc0, acc1;
        acc0  = w0.x * xv[0];
        acc1  = w0.y * xv[1];
        acc0 += w0.z * xv[2];
        acc1 += w0.w * xv[3];
        acc0 += w1.x * xv[4];
        acc1 += w1.y * xv[5];
        acc0 += w1.z * xv[6];
        acc1 += w1.w * xv[7];
        acc0 += w2.x * xv[8];
        acc1 += w2.y * xv[9];
        acc0 += w2.z * xv[10];
        acc1 += w2.w * xv[11];
        acc0 += w3.x * xv[12];
        acc1 += w3.y * xv[13];
        acc0 += w3.z * xv[14];
        acc1 += w3.w * xv[15];
        acc0 += w4r.x * xv[16];
        acc1 += w4r.y * xv[17];
        acc0 += w4r.z * xv[18];
        acc1 += w4r.w * xv[19];
        acc0 += w5.x * xv[20];
        acc1 += w5.y * xv[21];
        acc0 += w5.z * xv[22];
        acc1 += w5.w * xv[23];
        acc0 += w6.x * xv[24];
        xs[tid * Vv + u] = acc0 + acc1;
    }
    __syncthreads();

    float4* op4 = reinterpret_cast<float4*>(out + (size_t)b * (Tt * Vv));
    #pragma unroll
    for (int i = tid; i < (Tt * Vv) / 4; i += 128) __stcs(op4 + i, xs4[i]);
}

extern "C" void kernel_launch(void* const* d_in, const int* in_sizes, int n_in,
                              void* d_out, int out_size) {
    const float* x   = (const float*)d_in[0];
    const float* A   = (const float*)d_in[1];
    const float* w1  = (const float*)d_in[2];
    const float* b1  = (const float*)d_in[3];
    const float* w2  = (const float*)d_in[4];
    const float* b2  = (const float*)d_in[5];
    const float* w4  = (const float*)d_in[6];
    const float* b4  = (const float*)d_in[7];
    const float* sw1 = (const float*)d_in[8];
    const float* sb1 = (const float*)d_in[9];
    const float* sw2 = (const float*)d_in[10];
    const float* sb2 = (const float*)d_in[11];
    float* out = (float*)d_out;

    k1_meanT<<<Nn * Cc, 200>>>(x);
    k2_rel<<<Nn, 256>>>(w1, b1, w2, b2, sw1, sb1, sw2, sb2);
    k3_gemm<<<Nn * Cc, 128>>>(x, A, w4, b4, out);
}

// round 13
// speedup vs baseline: 1.2943x; 1.0034x over previous
#include <cuda_runtime.h>
#include <math.h>

// Problem constants
#define Nn 128
#define Cc 64
#define Tt 128
#define Vv 25
#define Rr 8
#define Hh 12

// Scratch (device globals; no allocation allowed)
__device__ float g_xm[Nn * Cc * Vv];                 // mean over T     (0.8 MB)
__device__ float g_relT[Nn * Vv * Vv * Rr];          // tanh relation, TRANSPOSED [n][e][r]
__device__ float g_a[Nn * Vv];                       // SE joint gate   (12.8 KB)

// ================= Kernel 1: xm[n,c,v] = mean_t x[n,c,t,v] =================
// Proven ~19.3us @ ~71% DRAM. Thread j loads float4s at j, j+200, j+400,
// j+600 (stride 800 floats == 0 mod 25 -> fixed v per component), then a
// conflict-free stride-25 shared reduction.
__global__ void __launch_bounds__(200) k1_meanT(const float* __restrict__ x) {
    const int b = blockIdx.x;                 // n*C + c
    const int j = threadIdx.x;                // 0..199
    const float4* xp4 = reinterpret_cast<const float4*>(x + (size_t)b * (Tt * Vv));

    float4 a0 = xp4[j];
    float4 a1 = xp4[j + 200];
    float4 a2 = xp4[j + 400];
    float4 a3 = xp4[j + 600];

    __shared__ float red[800];
    red[4 * j + 0] = a0.x + a1.x + a2.x + a3.x;
    red[4 * j + 1] = a0.y + a1.y + a2.y + a3.y;
    red[4 * j + 2] = a0.z + a1.z + a2.z + a3.z;
    red[4 * j + 3] = a0.w + a1.w + a2.w + a3.w;
    __syncthreads();

    if (j < Vv) {
        float tot = 0.f;
        #pragma unroll
        for (int p = 0; p < 32; p++) tot += red[j + Vv * p];
        g_xm[b * Vv + j] = tot * (1.0f / Tt);
    }
}

// ============ Kernel 2: SE gate + transposed relation tensor ============
// One block per n, 512 threads. Writes g_a[n,v] and g_relT[n][e=u*25+v][r]
// (r contiguous -> k3 reads 2 LDG.128 per element).
__global__ void __launch_bounds__(512) k2_rel(
        const float* __restrict__ w1, const float* __restrict__ b1,
        const float* __restrict__ w2, const float* __restrict__ b2,
        const float* __restrict__ sw1, const float* __restrict__ sb1,
        const float* __restrict__ sw2, const float* __restrict__ sb2) {
    const int n = blockIdx.x;
    const int tid = threadIdx.x;
    const int NT = 512;

    __shared__ float xm_sh[Cc * Vv];
    __shared__ float w1s[Rr * Cc], w2s[Rr * Cc];
    __shared__ float sw1s[Hh * Vv], sw2s[Vv * Hh];
    __shared__ float b1s[Rr], b2s[Rr], sb1s[Hh], sb2s[Vv];
    __shared__ float s_sh[Vv], h_sh[Hh];
    __shared__ float x1_sh[Rr * Vv], x2_sh[Rr * Vv];

    // xm load as float4 (1600 floats = 400 float4)
    {
        const float4* xm4 = reinterpret_cast<const float4*>(g_xm + n * Cc * Vv);
        float4* sh4 = reinterpret_cast<float4*>(xm_sh);
        if (tid < 400) sh4[tid] = xm4[tid];
    }
    for (int i = tid; i < Rr * Cc; i += NT) { w1s[i] = w1[i]; w2s[i] = w2[i]; }
    for (int i = tid; i < Hh * Vv; i += NT) { sw1s[i] = sw1[i]; sw2s[i] = sw2[i]; }
    if (tid < Rr) { b1s[tid] = b1[tid]; b2s[tid] = b2[tid]; }
    if (tid < Hh) sb1s[tid] = sb1[tid];
    if (tid < Vv) sb2s[tid] = sb2[tid];
    __syncthreads();

    // s[v] = mean_c xm
    if (tid < Vv) {
        float acc = 0.f;
        for (int c = 0; c < Cc; c++) acc += xm_sh[c * Vv + tid];
        s_sh[tid] = acc * (1.0f / Cc);
    }
    // x1[r,v], x2[r,v] (independent of s/h/a chain — run in parallel threads)
    if (tid >= 64 && tid < 64 + Rr * Vv) {
        int i = tid - 64;
        int r = i / Vv, v = i % Vv;
        float acc1 = b1s[r], acc2 = b2s[r];
        for (int c = 0; c < Cc; c++) {
            float xm = xm_sh[c * Vv + v];
            acc1 += w1s[r * Cc + c] * xm;
            acc2 += w2s[r * Cc + c] * xm;
        }
        x1_sh[i] = acc1;
        x2_sh[i] = acc2;
    }
    __syncthreads();
    if (tid < Hh) {
        float acc = sb1s[tid];
        for (int v = 0; v < Vv; v++) acc += sw1s[tid * Vv + v] * s_sh[v];
        h_sh[tid] = fmaxf(acc, 0.f);
    }
    __syncthreads();
    if (tid < Vv) {
        float acc = sb2s[tid];
        for (int q = 0; q < Hh; q++) acc += sw2s[tid * Hh + q] * h_sh[q];
        g_a[n * Vv + tid] = 1.0f / (1.0f + expf(-acc));
    }

    // relT[e][r] = tanh(x1[r,u] - x2[r,v]), e = u*25+v; 8 r's packed per e.
    float4* relp4 = reinterpret_cast<float4*>(g_relT + (size_t)n * (Vv * Vv * Rr));
    for (int e = tid; e < Vv * Vv; e += NT) {
        const int u = e / Vv, v = e % Vv;
        float4 lo, hi;
        lo.x = tanhf(x1_sh[0 * Vv + u] - x2_sh[0 * Vv + v]);
        lo.y = tanhf(x1_sh[1 * Vv + u] - x2_sh[1 * Vv + v]);
        lo.z = tanhf(x1_sh[2 * Vv + u] - x2_sh[2 * Vv + v]);
        lo.w = tanhf(x1_sh[3 * Vv + u] - x2_sh[3 * Vv + v]);
        hi.x = tanhf(x1_sh[4 * Vv + u] - x2_sh[4 * Vv + v]);
        hi.y = tanhf(x1_sh[5 * Vv + u] - x2_sh[5 * Vv + v]);
        hi.z = tanhf(x1_sh[6 * Vv + u] - x2_sh[6 * Vv + v]);
        hi.w = tanhf(x1_sh[7 * Vv + u] - x2_sh[7 * Vv + v]);
        relp4[2 * e]     = lo;
        relp4[2 * e + 1] = hi;
    }
}

// ============ Kernel 3 (proven 70.3us body): recon + GEMM ============
// One block per (n,c), 128 threads, one t-row per thread. Recon now reads
// relT with 2 coalesced LDG.128 per element (was 8 scattered LDG.32).
__global__ void __launch_bounds__(128, 10) k3_gemm(const float* __restrict__ x,
                                                   const float* __restrict__ Astat,
                                                   const float* __restrict__ w4,
                                                   const float* __restrict__ b4,
                                                   float* __restrict__ out) {
    __shared__ float xs[Tt * Vv];                      // 12.8 KB; reused as out staging
    __shared__ __align__(16) float Ws[Vv * 28];        // padded rows: 112 B each

    const int b = blockIdx.x;           // n*C + c
    const int n = b >> 6;
    const int c = b & 63;
    const int tid = threadIdx.x;        // 0..127 == t

    // Load x tile (800 float4, coalesced)
    const float4* xp4 = reinterpret_cast<const float4*>(x + (size_t)b * (Tt * Vv));
    float4* xs4 = reinterpret_cast<float4*>(xs);
    #pragma unroll
    for (int i = tid; i < (Tt * Vv) / 4; i += 128) xs4[i] = xp4[i];

    // Zero padding columns 25..27 of Ws
    if (tid < Vv * 3) {
        int u = tid / 3, p = tid % 3;
        Ws[u * 28 + 25 + p] = 0.f;
    }

    // Reconstruct weight matrix from relT (coalesced float4 reads):
    // Ws[u,v] = (sum_r w4[c,r]*relT[e][r] + b4[c] + A[u,v]) * a[n,v]
    {
        const float4 wA = *reinterpret_cast<const float4*>(w4 + c * Rr);
        const float4 wB = *reinterpret_cast<const float4*>(w4 + c * Rr + 4);
        const float bias = __ldg(b4 + c);
        const float4* relp4 = reinterpret_cast<const float4*>(g_relT + (size_t)n * (Vv * Vv * Rr));
        const float* ap = g_a + n * Vv;
        #pragma unroll 1
        for (int e = tid; e < Vv * Vv; e += 128) {
            int u = e / Vv, v = e - u * Vv;
            float4 lo = relp4[2 * e];
            float4 hi = relp4[2 * e + 1];
            float acc = bias + __ldg(Astat + e);
            acc += wA.x * lo.x + wA.y * lo.y + wA.z * lo.z + wA.w * lo.w;
            acc += wB.x * hi.x + wB.y * hi.y + wB.z * hi.z + wB.w * hi.w;
            Ws[u * 28 + v] = acc * __ldg(ap + v);
        }
    }
    __syncthreads();

    // Pull this thread's x row into registers (lane stride 25 ⊥ 32: conflict-free)
    float xv[Vv];
    #pragma unroll
    for (int v = 0; v < Vv; v++) xv[v] = xs[tid * Vv + v];
    __syncthreads();   // xs now free for output staging

    #pragma unroll 1
    for (int u = 0; u < Vv; u++) {
        const float4* wr = reinterpret_cast<const float4*>(Ws + u * 28);
        float4 w0 = wr[0], w1 = wr[1], w2 = wr[2], w3 = wr[3];
        float4 w4r = wr[4], w5 = wr[5], w6 = wr[6];
        float acc0, acc1;
        acc0  = w0.x * xv[0];
        acc1  = w0.y * xv[1];
        acc0 += w0.z * xv[2];
        acc1 += w0.w * xv[3];
        acc0 += w1.x * xv[4];
        acc1 += w1.y * xv[5];
        acc0 += w1.z * xv[6];
        acc1 += w1.w * xv[7];
        acc0 += w2.x * xv[8];
        acc1 += w2.y * xv[9];
        acc0 += w2.z * xv[10];
        acc1 += w2.w * xv[11];
        acc0 += w3.x * xv[12];
        acc1 += w3.y * xv[13];
        acc0 += w3.z * xv[14];
        acc1 += w3.w * xv[15];
        acc0 += w4r.x * xv[16];
        acc1 += w4r.y * xv[17];
        acc0 += w4r.z * xv[18];
        acc1 += w4r.w * xv[19];
        acc0 += w5.x * xv[20];
        acc1 += w5.y * xv[21];
        acc0 += w5.z * xv[22];
        acc1 += w5.w * xv[23];
        acc0 += w6.x * xv[24];
        xs[tid * Vv + u] = acc0 + acc1;
    }
    __syncthreads();

    float4* op4 = reinterpret_cast<float4*>(out + (size_t)b * (Tt * Vv));
    #pragma unroll
    for (int i = tid; i < (Tt * Vv) / 4; i += 128) __stcs(op4 + i, xs4[i]);
}

extern "C" void kernel_launch(void* const* d_in, const int* in_sizes, int n_in,
                              void* d_out, int out_size) {
    const float* x   = (const float*)d_in[0];
    const float* A   = (const float*)d_in[1];
    const float* w1  = (const float*)d_in[2];
    const float* b1  = (const float*)d_in[3];
    const float* w2  = (const float*)d_in[4];
    const float* b2  = (const float*)d_in[5];
    const float* w4  = (const float*)d_in[6];
    const float* b4  = (const float*)d_in[7];
    const float* sw1 = (const float*)d_in[8];
    const float* sb1 = (const float*)d_in[9];
    const float* sw2 = (const float*)d_in[10];
    const float* sb2 = (const float*)d_in[11];
    float* out = (float*)d_out;

    k1_meanT<<<Nn * Cc, 200>>>(x);
    k2_rel<<<Nn, 512>>>(w1, b1, w2, b2, sw1, sb1, sw2, sb2);
    k3_gemm<<<Nn * Cc, 128>>>(x, A, w4, b4, out);
}